// round 14
// baseline (speedup 1.0000x reference)
#include <cuda_runtime.h>
#include <cuda_bf16.h>
#include <cuda_fp16.h>
#include <cstdint>

#define NN 40000
#define EE 640000
#define DD 128
#define LN_EPS 1e-5f
#define SCAN_BLKS 157   // ceil(40000/256)
#define KPAD 136
#define WH_ELEMS (3 * 128 * KPAD)

// ================= device scratch =================
__device__ unsigned long long g_deg[NN];          // packed cnt<<44 | fx24
__device__ __align__(16) float g_dinv[NN];
__device__ int   g_rowptr[NN + 1];
__device__ int   g_cursor[NN];
__device__ int   g_part[SCAN_BLKS];
__device__ int   g_done;
__device__ __align__(16) uint2 g_cv[EE];          // packed {col, val bits}
__device__ __align__(16) uint2 g_xh[(size_t)NN * 32];   // x fp16 (GEMM hop0)
__device__ __align__(16) float g_t1f[(size_t)NN * DD];  // T1 fp32 (pass-2 gather)
__device__ __align__(16) uint2 g_t1h[(size_t)NN * 32];  // T1 fp16 (GEMM)
__device__ __align__(16) uint2 g_t2h[(size_t)NN * 32];  // T2 fp16 (GEMM)
__device__ __align__(16) __half g_wh[WH_ELEMS];   // W fp16, [p][n][KPAD]
__device__ int   g_tile_ctr;

// ========= K1: fused convert(x->fp16) + W->fp16 transpose + degree =========
__global__ void convert_degree_kernel(const float* __restrict__ x,
                                      const float* __restrict__ W,
                                      const int* __restrict__ ei,
                                      const float* __restrict__ w) {
    int i = blockIdx.x * blockDim.x + threadIdx.x;
    if (i == 0) g_done = 0;
    if (i < NN * 32) {
        float4 v = ((const float4*)x)[i];
        __half2 a = __floats2half2_rn(v.x, v.y);
        __half2 b = __floats2half2_rn(v.z, v.w);
        uint2 u;
        u.x = *reinterpret_cast<uint32_t*>(&a);
        u.y = *reinterpret_cast<uint32_t*>(&b);
        g_xh[i] = u;
    }
    if (i < 3 * 16384) {             // W: [p][k][n] -> g_wh [p][n][KPAD]
        int p = i >> 14;
        int r = i & 16383;
        int k = r >> 7, n = r & 127;
        g_wh[p * 128 * KPAD + n * KPAD + k] = __float2half_rn(W[i]);
    }
    if (i < EE) {
        int r = ei[i];
        if ((unsigned)r < NN) {
            unsigned long long fx =
                (unsigned long long)(w[i] * 16777216.0f);   // w * 2^24
            atomicAdd(&g_deg[r], (1ull << 44) | fx);         // non-returning
        }
    }
}

// ========== K2: fused scan (publish partial, barrier, apply) ==============
__global__ void scan_fused_kernel() {
    __shared__ int pex[SCAN_BLKS];
    __shared__ int ws2[8];
    __shared__ int ws[8];
    int tid = threadIdx.x;
    int lane = tid & 31, wid = tid >> 5;
    int b = blockIdx.x;

    // --- local block scan of counts ---
    int i = b * 256 + tid;
    unsigned long long pk = (i < NN) ? g_deg[i] : 0ull;
    int v = (int)(pk >> 44);
    int s = v;
    #pragma unroll
    for (int o = 1; o < 32; o <<= 1) {
        int t = __shfl_up_sync(0xffffffffu, s, o);
        if (lane >= o) s += t;
    }
    if (lane == 31) ws[wid] = s;
    __syncthreads();
    if (wid == 0 && lane < 8) {
        int t = ws[lane];
        #pragma unroll
        for (int o = 1; o < 8; o <<= 1) {
            int u = __shfl_up_sync(0xffu, t, o);
            if (lane >= o) t += u;
        }
        ws[lane] = t;
    }
    __syncthreads();
    int excl_local = s - v + (wid ? ws[wid - 1] : 0);

    // --- publish block total, wait for all blocks (all co-resident) ---
    if (tid == 0) {
        g_part[b] = ws[7];
        __threadfence();
        atomicAdd(&g_done, 1);
        while (*(volatile int*)&g_done < SCAN_BLKS) { }
        __threadfence();
    }
    __syncthreads();

    // --- parallel exclusive scan of the 157 partials (per block) ---
    int pv = (tid < SCAN_BLKS) ? *(volatile int*)&g_part[tid] : 0;
    int ps = pv;
    #pragma unroll
    for (int o = 1; o < 32; o <<= 1) {
        int t = __shfl_up_sync(0xffffffffu, ps, o);
        if (lane >= o) ps += t;
    }
    if (lane == 31) ws2[wid] = ps;
    __syncthreads();
    if (wid == 0 && lane < 8) {
        int t = ws2[lane];
        #pragma unroll
        for (int o = 1; o < 8; o <<= 1) {
            int u = __shfl_up_sync(0xffu, t, o);
            if (lane >= o) t += u;
        }
        ws2[lane] = t;
    }
    __syncthreads();
    if (tid < SCAN_BLKS)
        pex[tid] = ps - pv + (wid ? ws2[wid - 1] : 0);
    __syncthreads();

    int excl = excl_local + pex[b];
    if (i < NN) {
        g_rowptr[i] = excl;
        g_cursor[i] = excl;
        float dg = (float)(pk & ((1ull << 44) - 1)) * 5.9604644775390625e-8f;
        g_dinv[i] = (dg > 0.f) ? rsqrtf(dg) : 0.f;
        g_deg[i] = 0ull;            // ready for next replay
    }
    if (i == 0) {
        g_tile_ctr = 0;
        g_rowptr[NN] = EE;
    }
}

// ============ K3: scatter, 2 edges/thread (cursor atomics) =================
__global__ void scatter_kernel(const int* __restrict__ ei,
                               const float* __restrict__ w) {
    int t = blockIdx.x * blockDim.x + threadIdx.x;
    int e = t * 2;
    if (e >= EE) return;
    int2   rr = *(const int2*)(ei + e);
    int2   cc = *(const int2*)(ei + EE + e);
    float2 ww = *(const float2*)(w + e);
    bool ok0 = (unsigned)rr.x < NN && (unsigned)cc.x < NN;
    bool ok1 = (unsigned)rr.y < NN && (unsigned)cc.y < NN;
    float val0 = ok0 ? -g_dinv[rr.x] * ww.x * g_dinv[cc.x] : 0.f;
    float val1 = ok1 ? -g_dinv[rr.y] * ww.y * g_dinv[cc.y] : 0.f;
    int pos0 = ok0 ? atomicAdd(&g_cursor[rr.x], 1) : 0;
    int pos1 = ok1 ? atomicAdd(&g_cursor[rr.y], 1) : 0;
    if (ok0) {
        uint2 cv; cv.x = (uint32_t)cc.x; cv.y = __float_as_uint(val0);
        g_cv[pos0] = cv;
    }
    if (ok1) {
        uint2 cv; cv.x = (uint32_t)cc.y; cv.y = __float_as_uint(val1);
        g_cv[pos1] = cv;
    }
}

// ======= K4/K5: SpMM fp32 gather / fp16(+fp32) out (unroll 2) =============
// acc = Σ val*X[col];  Yh = fp16(alpha*acc [- Xsub]);  Yf (opt) = fp32 same
__global__ void spmm_kernel(const float* __restrict__ X,
                            float* __restrict__ Yf,
                            uint2* __restrict__ Yh,
                            const float* __restrict__ Xsub,
                            float alpha) {
    int gw = (blockIdx.x * blockDim.x + threadIdx.x) >> 5;
    if (gw >= NN) return;
    int lane = threadIdx.x & 31;
    int s = g_rowptr[gw], e2 = g_rowptr[gw + 1];
    const float4* Xv = (const float4*)X;
    float4 acc = make_float4(0.f, 0.f, 0.f, 0.f);
    int j = s;
    for (; j + 1 < e2; j += 2) {
        uint2 cv0 = g_cv[j], cv1 = g_cv[j + 1];
        float4 x0 = Xv[(size_t)cv0.x * 32 + lane];
        float4 x1 = Xv[(size_t)cv1.x * 32 + lane];
        float v0 = __uint_as_float(cv0.y), v1 = __uint_as_float(cv1.y);
        acc.x += v0 * x0.x; acc.y += v0 * x0.y; acc.z += v0 * x0.z; acc.w += v0 * x0.w;
        acc.x += v1 * x1.x; acc.y += v1 * x1.y; acc.z += v1 * x1.z; acc.w += v1 * x1.w;
    }
    if (j < e2) {
        uint2 cv0 = g_cv[j];
        float4 x0 = Xv[(size_t)cv0.x * 32 + lane];
        float v0 = __uint_as_float(cv0.y);
        acc.x += v0 * x0.x; acc.y += v0 * x0.y; acc.z += v0 * x0.z; acc.w += v0 * x0.w;
    }
    float4 o;
    if (Xsub) {
        float4 xs = ((const float4*)Xsub)[(size_t)gw * 32 + lane];
        o.x = alpha * acc.x - xs.x;
        o.y = alpha * acc.y - xs.y;
        o.z = alpha * acc.z - xs.z;
        o.w = alpha * acc.w - xs.w;
    } else {
        o.x = alpha * acc.x; o.y = alpha * acc.y;
        o.z = alpha * acc.z; o.w = alpha * acc.w;
    }
    if (Yf) ((float4*)Yf)[(size_t)gw * 32 + lane] = o;
    __half2 ha = __floats2half2_rn(o.x, o.y);
    __half2 hb = __floats2half2_rn(o.z, o.w);
    uint2 u;
    u.x = *reinterpret_cast<uint32_t*>(&ha);
    u.y = *reinterpret_cast<uint32_t*>(&hb);
    Yh[(size_t)gw * 32 + lane] = u;
}

// ====== K6: fp16 mma GEMM (all-fp16 A operands) + bias + LN + ReLU =========
#define NT 313
#define MAT_BYTES (128 * KPAD * 2)
#define OFF_BIAS  (3 * MAT_BYTES)
#define OFF_GAMMA (OFF_BIAS + 512)
#define OFF_BETA  (OFF_GAMMA + 512)
#define GEMM_SMEM (OFF_BETA + 512)      // 105984 (x2 CTAs)

__device__ __forceinline__ void mma_f16(float* c, const uint32_t* a,
                                        uint32_t b0, uint32_t b1) {
    asm volatile(
        "mma.sync.aligned.m16n8k16.row.col.f32.f16.f16.f32 "
        "{%0,%1,%2,%3}, {%4,%5,%6,%7}, {%8,%9}, {%0,%1,%2,%3};"
        : "+f"(c[0]), "+f"(c[1]), "+f"(c[2]), "+f"(c[3])
        : "r"(a[0]), "r"(a[1]), "r"(a[2]), "r"(a[3]), "r"(b0), "r"(b1));
}

__global__ __launch_bounds__(256, 2)
void gemm_mma_kernel(const char* __restrict__ X0,     // fp16 rows, 256B/row
                     const char* __restrict__ X1,     // fp16 rows
                     const char* __restrict__ X2,     // fp16 rows
                     const float* __restrict__ bias,
                     const float* __restrict__ gamma,
                     const float* __restrict__ beta,
                     float* __restrict__ out) {
    extern __shared__ char smem[];
    __shared__ int s_tile;
    int tid = threadIdx.x;
    int wid = tid >> 5, lane = tid & 31;
    int tig = lane & 3, gid = lane >> 2;

    float* sBias  = (float*)(smem + OFF_BIAS);
    float* sGamma = (float*)(smem + OFF_GAMMA);
    float* sBeta  = (float*)(smem + OFF_BETA);
    if (tid < 128) {
        sBias[tid]  = bias[tid];
        sGamma[tid] = gamma[tid];
        sBeta[tid]  = beta[tid];
    }

    // stage pre-converted W: vector memcpy (6528 uint4)
    {
        const uint4* src = (const uint4*)g_wh;
        uint4* dst = (uint4*)smem;
        for (int idx = tid; idx < WH_ELEMS / 8; idx += 256)
            dst[idx] = src[idx];
    }
    __syncthreads();

    for (;;) {
        if (tid == 0) s_tile = atomicAdd(&g_tile_ctr, 1);
        __syncthreads();
        int tile = s_tile;
        if (tile >= NT) break;
        int row0 = tile * 128;

        int r0 = row0 + wid * 16 + gid;
        bool v0 = r0 < NN, v1 = (r0 + 8) < NN;

        float cacc[16][4];
        #pragma unroll
        for (int nt = 0; nt < 16; nt++)
            #pragma unroll
            for (int j = 0; j < 4; j++) cacc[nt][j] = 0.f;

        const char* mw0 = smem;
        const char* mw1 = smem + MAT_BYTES;
        const char* mw2 = smem + 2 * MAT_BYTES;

        #pragma unroll 1
        for (int ks = 0; ks < 8; ks++) {
            int k0 = ks * 16 + tig * 2;
            size_t o0 = (size_t)r0 * 256 + k0 * 2;
            size_t o1 = (size_t)(r0 + 8) * 256 + k0 * 2;
            uint32_t a0[4], a1[4], a2[4];
            a0[0] = v0 ? *(const uint32_t*)(X0 + o0) : 0u;
            a0[1] = v1 ? *(const uint32_t*)(X0 + o1) : 0u;
            a0[2] = v0 ? *(const uint32_t*)(X0 + o0 + 16) : 0u;
            a0[3] = v1 ? *(const uint32_t*)(X0 + o1 + 16) : 0u;
            a1[0] = v0 ? *(const uint32_t*)(X1 + o0) : 0u;
            a1[1] = v1 ? *(const uint32_t*)(X1 + o1) : 0u;
            a1[2] = v0 ? *(const uint32_t*)(X1 + o0 + 16) : 0u;
            a1[3] = v1 ? *(const uint32_t*)(X1 + o1 + 16) : 0u;
            a2[0] = v0 ? *(const uint32_t*)(X2 + o0) : 0u;
            a2[1] = v1 ? *(const uint32_t*)(X2 + o1) : 0u;
            a2[2] = v0 ? *(const uint32_t*)(X2 + o0 + 16) : 0u;
            a2[3] = v1 ? *(const uint32_t*)(X2 + o1 + 16) : 0u;

            #pragma unroll
            for (int nt = 0; nt < 16; nt++) {
                int n = nt * 8 + gid;
                size_t boff = ((size_t)n * KPAD + k0) * 2;
                uint32_t b0 = *(const uint32_t*)(mw0 + boff);
                uint32_t b1 = *(const uint32_t*)(mw0 + boff + 16);
                mma_f16(cacc[nt], a0, b0, b1);
                b0 = *(const uint32_t*)(mw1 + boff);
                b1 = *(const uint32_t*)(mw1 + boff + 16);
                mma_f16(cacc[nt], a1, b0, b1);
                b0 = *(const uint32_t*)(mw2 + boff);
                b1 = *(const uint32_t*)(mw2 + boff + 16);
                mma_f16(cacc[nt], a2, b0, b1);
            }
        }

        #pragma unroll
        for (int h = 0; h < 2; h++) {
            int r = r0 + h * 8;
            float s1 = 0.f, s2 = 0.f;
            #pragma unroll
            for (int nt = 0; nt < 16; nt++) {
                int col = nt * 8 + tig * 2;
                float a = cacc[nt][2 * h + 0] + sBias[col];
                float b = cacc[nt][2 * h + 1] + sBias[col + 1];
                cacc[nt][2 * h + 0] = a;
                cacc[nt][2 * h + 1] = b;
                s1 += a + b;
                s2 += a * a + b * b;
            }
            s1 += __shfl_xor_sync(0xffffffffu, s1, 1);
            s2 += __shfl_xor_sync(0xffffffffu, s2, 1);
            s1 += __shfl_xor_sync(0xffffffffu, s1, 2);
            s2 += __shfl_xor_sync(0xffffffffu, s2, 2);
            float mean = s1 * (1.f / 128.f);
            float var  = s2 * (1.f / 128.f) - mean * mean;
            float inv  = rsqrtf(var + LN_EPS);
            if (r < NN) {
                #pragma unroll
                for (int nt = 0; nt < 16; nt++) {
                    int col = nt * 8 + tig * 2;
                    float2 o;
                    o.x = fmaxf((cacc[nt][2 * h] - mean) * inv * sGamma[col]
                                + sBeta[col], 0.f);
                    o.y = fmaxf((cacc[nt][2 * h + 1] - mean) * inv * sGamma[col + 1]
                                + sBeta[col + 1], 0.f);
                    *(float2*)(out + (size_t)r * 128 + col) = o;
                }
            }
        }
        __syncthreads();
    }
}

// ================= launch =================
extern "C" void kernel_launch(void* const* d_in, const int* in_sizes, int n_in,
                              void* d_out, int out_size) {
    const float* x     = (const float*)d_in[0];
    const float* ew    = (const float*)d_in[1];
    const float* W     = (const float*)d_in[2];
    const float* bias  = (const float*)d_in[3];
    const float* gamma = (const float*)d_in[4];
    const float* beta  = (const float*)d_in[5];
    const int*   ei    = (const int*)d_in[6];
    float* out = (float*)d_out;

    uint2 *Xh, *T1h, *T2h;
    float *T1f;
    cudaGetSymbolAddress((void**)&Xh, g_xh);
    cudaGetSymbolAddress((void**)&T1f, g_t1f);
    cudaGetSymbolAddress((void**)&T1h, g_t1h);
    cudaGetSymbolAddress((void**)&T2h, g_t2h);

    cudaFuncSetAttribute(gemm_mma_kernel,
                         cudaFuncAttributeMaxDynamicSharedMemorySize,
                         GEMM_SMEM);

    convert_degree_kernel<<<(NN * 32 + 255) / 256, 256>>>(x, W, ei, ew);
    scan_fused_kernel<<<SCAN_BLKS, 256>>>();
    scatter_kernel<<<(EE / 2 + 255) / 256, 256>>>(ei, ew);

    // T1 = L x  (gather fp32 x; write T1f fp32 + T1h fp16)
    spmm_kernel<<<(NN * 32 + 255) / 256, 256>>>(x, T1f, T1h, nullptr, 1.0f);
    // T2 = 2 L T1 - x  (gather fp32 T1f; write T2h fp16)
    spmm_kernel<<<(NN * 32 + 255) / 256, 256>>>(T1f, nullptr, T2h, x, 2.0f);

    gemm_mma_kernel<<<296, 256, GEMM_SMEM>>>((const char*)Xh, (const char*)T1h,
                                             (const char*)T2h,
                                             bias, gamma, beta, out);
}

// round 15
// speedup vs baseline: 1.1095x; 1.1095x over previous
#include <cuda_runtime.h>
#include <cuda_bf16.h>
#include <cuda_fp16.h>
#include <cstdint>

#define NN 40000
#define EE 640000
#define DD 128
#define LN_EPS 1e-5f
#define SCAN_BLKS 157   // ceil(40000/256)
#define KPAD 136
#define WH_ELEMS (3 * 128 * KPAD)

// ================= device scratch =================
__device__ unsigned long long g_deg[NN];          // packed cnt<<44 | fx24
__device__ __align__(16) float g_dinv[NN];
__device__ int   g_rowptr[NN + 1];
__device__ int   g_cursor[NN];
__device__ int   g_part[SCAN_BLKS];
__device__ int   g_done;
__device__ __align__(16) uint2 g_cv[EE];          // packed {col, val bits}
__device__ __align__(16) uint2 g_xh[(size_t)NN * 32];   // x fp16
__device__ __align__(16) uint2 g_t1h[(size_t)NN * 32];  // T1 fp16
__device__ __align__(16) uint2 g_t2h[(size_t)NN * 32];  // T2 fp16
__device__ __align__(16) __half g_wh[WH_ELEMS];   // W fp16, [p][n][KPAD]
__device__ int   g_tile_ctr;

// ========= K1: fused convert(x->fp16) + W->fp16 transpose + degree =========
__global__ void convert_degree_kernel(const float* __restrict__ x,
                                      const float* __restrict__ W,
                                      const int* __restrict__ ei,
                                      const float* __restrict__ w) {
    int i = blockIdx.x * blockDim.x + threadIdx.x;
    if (i == 0) g_done = 0;
    if (i < NN * 32) {
        float4 v = ((const float4*)x)[i];
        __half2 a = __floats2half2_rn(v.x, v.y);
        __half2 b = __floats2half2_rn(v.z, v.w);
        uint2 u;
        u.x = *reinterpret_cast<uint32_t*>(&a);
        u.y = *reinterpret_cast<uint32_t*>(&b);
        g_xh[i] = u;
    }
    if (i < 3 * 16384) {             // W: [p][k][n] -> g_wh [p][n][KPAD]
        int p = i >> 14;
        int r = i & 16383;
        int k = r >> 7, n = r & 127;
        g_wh[p * 128 * KPAD + n * KPAD + k] = __float2half_rn(W[i]);
    }
    if (i < EE) {
        int r = ei[i];
        if ((unsigned)r < NN) {
            unsigned long long fx =
                (unsigned long long)(w[i] * 16777216.0f);   // w * 2^24
            atomicAdd(&g_deg[r], (1ull << 44) | fx);         // non-returning
        }
    }
}

// ==== K2: fused scan + scatter (two grid-wide spin barriers) ===============
__global__ void scan_scatter_kernel(const int* __restrict__ ei,
                                    const float* __restrict__ w) {
    __shared__ int pex[SCAN_BLKS];
    __shared__ int ws2[8];
    __shared__ int ws[8];
    int tid = threadIdx.x;
    int lane = tid & 31, wid = tid >> 5;
    int b = blockIdx.x;

    // --- local block scan of counts ---
    int i = b * 256 + tid;
    unsigned long long pk = (i < NN) ? g_deg[i] : 0ull;
    int v = (int)(pk >> 44);
    int s = v;
    #pragma unroll
    for (int o = 1; o < 32; o <<= 1) {
        int t = __shfl_up_sync(0xffffffffu, s, o);
        if (lane >= o) s += t;
    }
    if (lane == 31) ws[wid] = s;
    __syncthreads();
    if (wid == 0 && lane < 8) {
        int t = ws[lane];
        #pragma unroll
        for (int o = 1; o < 8; o <<= 1) {
            int u = __shfl_up_sync(0xffu, t, o);
            if (lane >= o) t += u;
        }
        ws[lane] = t;
    }
    __syncthreads();
    int excl_local = s - v + (wid ? ws[wid - 1] : 0);

    // --- barrier 1: publish block totals ---
    if (tid == 0) {
        g_part[b] = ws[7];
        __threadfence();
        atomicAdd(&g_done, 1);
        while (*(volatile int*)&g_done < SCAN_BLKS) { }
        __threadfence();
    }
    __syncthreads();

    // --- parallel exclusive scan of the 157 partials (per block) ---
    int pv = (tid < SCAN_BLKS) ? *(volatile int*)&g_part[tid] : 0;
    int ps = pv;
    #pragma unroll
    for (int o = 1; o < 32; o <<= 1) {
        int t = __shfl_up_sync(0xffffffffu, ps, o);
        if (lane >= o) ps += t;
    }
    if (lane == 31) ws2[wid] = ps;
    __syncthreads();
    if (wid == 0 && lane < 8) {
        int t = ws2[lane];
        #pragma unroll
        for (int o = 1; o < 8; o <<= 1) {
            int u = __shfl_up_sync(0xffu, t, o);
            if (lane >= o) t += u;
        }
        ws2[lane] = t;
    }
    __syncthreads();
    if (tid < SCAN_BLKS)
        pex[tid] = ps - pv + (wid ? ws2[wid - 1] : 0);
    __syncthreads();

    int excl = excl_local + pex[b];
    if (i < NN) {
        g_rowptr[i] = excl;
        g_cursor[i] = excl;
        float dg = (float)(pk & ((1ull << 44) - 1)) * 5.9604644775390625e-8f;
        g_dinv[i] = (dg > 0.f) ? rsqrtf(dg) : 0.f;
        g_deg[i] = 0ull;            // ready for next replay
    }
    if (i == 0) {
        g_tile_ctr = 0;
        g_rowptr[NN] = EE;
    }

    // --- barrier 2: all cursors/dinv visible before scatter ---
    __threadfence();
    __syncthreads();
    if (tid == 0) {
        atomicAdd(&g_done, 1);
        while (*(volatile int*)&g_done < 2 * SCAN_BLKS) { }
        __threadfence();
    }
    __syncthreads();

    // --- scatter phase: stride over edge pairs ---
    const int stride = SCAN_BLKS * 256 * 2;
    for (int e = (b * 256 + tid) * 2; e < EE; e += stride) {
        int2   rr = *(const int2*)(ei + e);
        int2   cc = *(const int2*)(ei + EE + e);
        float2 ww = *(const float2*)(w + e);
        bool ok0 = (unsigned)rr.x < NN && (unsigned)cc.x < NN;
        bool ok1 = (unsigned)rr.y < NN && (unsigned)cc.y < NN;
        float val0 = ok0 ? -g_dinv[rr.x] * ww.x * g_dinv[cc.x] : 0.f;
        float val1 = ok1 ? -g_dinv[rr.y] * ww.y * g_dinv[cc.y] : 0.f;
        int pos0 = ok0 ? atomicAdd(&g_cursor[rr.x], 1) : 0;
        int pos1 = ok1 ? atomicAdd(&g_cursor[rr.y], 1) : 0;
        if (ok0) {
            uint2 cv; cv.x = (uint32_t)cc.x; cv.y = __float_as_uint(val0);
            g_cv[pos0] = cv;
        }
        if (ok1) {
            uint2 cv; cv.x = (uint32_t)cc.y; cv.y = __float_as_uint(val1);
            g_cv[pos1] = cv;
        }
    }
}

// ============ K4/K5: SpMM fp16 in / fp16 out (unroll 4) ====================
__global__ void spmm_kernel(const uint2* __restrict__ Xh,
                            uint2* __restrict__ Yh,
                            const uint2* __restrict__ XsubH,
                            float alpha) {
    int gw = (blockIdx.x * blockDim.x + threadIdx.x) >> 5;
    if (gw >= NN) return;
    int lane = threadIdx.x & 31;
    int s = g_rowptr[gw], e2 = g_rowptr[gw + 1];
    float4 acc = make_float4(0.f, 0.f, 0.f, 0.f);
    int cnt4 = (e2 - s) & ~3;
    int j = s;
    for (; j < s + cnt4; j += 4) {
        uint2 cv0 = g_cv[j],     cv1 = g_cv[j + 1];
        uint2 cv2 = g_cv[j + 2], cv3 = g_cv[j + 3];
        uint2 h0 = Xh[(size_t)cv0.x * 32 + lane];
        uint2 h1 = Xh[(size_t)cv1.x * 32 + lane];
        uint2 h2 = Xh[(size_t)cv2.x * 32 + lane];
        uint2 h3 = Xh[(size_t)cv3.x * 32 + lane];
        float v0 = __uint_as_float(cv0.y), v1 = __uint_as_float(cv1.y);
        float v2 = __uint_as_float(cv2.y), v3 = __uint_as_float(cv3.y);
        float2 a0 = __half22float2(*reinterpret_cast<__half2*>(&h0.x));
        float2 b0 = __half22float2(*reinterpret_cast<__half2*>(&h0.y));
        float2 a1 = __half22float2(*reinterpret_cast<__half2*>(&h1.x));
        float2 b1 = __half22float2(*reinterpret_cast<__half2*>(&h1.y));
        float2 a2 = __half22float2(*reinterpret_cast<__half2*>(&h2.x));
        float2 b2 = __half22float2(*reinterpret_cast<__half2*>(&h2.y));
        float2 a3 = __half22float2(*reinterpret_cast<__half2*>(&h3.x));
        float2 b3 = __half22float2(*reinterpret_cast<__half2*>(&h3.y));
        acc.x += v0 * a0.x; acc.y += v0 * a0.y; acc.z += v0 * b0.x; acc.w += v0 * b0.y;
        acc.x += v1 * a1.x; acc.y += v1 * a1.y; acc.z += v1 * b1.x; acc.w += v1 * b1.y;
        acc.x += v2 * a2.x; acc.y += v2 * a2.y; acc.z += v2 * b2.x; acc.w += v2 * b2.y;
        acc.x += v3 * a3.x; acc.y += v3 * a3.y; acc.z += v3 * b3.x; acc.w += v3 * b3.y;
    }
    for (; j < e2; j++) {
        uint2 cv0 = g_cv[j];
        uint2 h0 = Xh[(size_t)cv0.x * 32 + lane];
        float v0 = __uint_as_float(cv0.y);
        float2 a0 = __half22float2(*reinterpret_cast<__half2*>(&h0.x));
        float2 b0 = __half22float2(*reinterpret_cast<__half2*>(&h0.y));
        acc.x += v0 * a0.x; acc.y += v0 * a0.y; acc.z += v0 * b0.x; acc.w += v0 * b0.y;
    }
    float4 o;
    if (XsubH) {
        uint2 xs = XsubH[(size_t)gw * 32 + lane];
        float2 xa = __half22float2(*reinterpret_cast<__half2*>(&xs.x));
        float2 xb = __half22float2(*reinterpret_cast<__half2*>(&xs.y));
        o.x = alpha * acc.x - xa.x;
        o.y = alpha * acc.y - xa.y;
        o.z = alpha * acc.z - xb.x;
        o.w = alpha * acc.w - xb.y;
    } else {
        o.x = alpha * acc.x; o.y = alpha * acc.y;
        o.z = alpha * acc.z; o.w = alpha * acc.w;
    }
    __half2 ha = __floats2half2_rn(o.x, o.y);
    __half2 hb = __floats2half2_rn(o.z, o.w);
    uint2 u;
    u.x = *reinterpret_cast<uint32_t*>(&ha);
    u.y = *reinterpret_cast<uint32_t*>(&hb);
    Yh[(size_t)gw * 32 + lane] = u;
}

// ====== K6: fp16 mma GEMM (all-fp16 A operands) + bias + LN + ReLU =========
#define NT 313
#define MAT_BYTES (128 * KPAD * 2)
#define OFF_BIAS  (3 * MAT_BYTES)
#define OFF_GAMMA (OFF_BIAS + 512)
#define OFF_BETA  (OFF_GAMMA + 512)
#define GEMM_SMEM (OFF_BETA + 512)      // 105984 (x2 CTAs)

__device__ __forceinline__ void mma_f16(float* c, const uint32_t* a,
                                        uint32_t b0, uint32_t b1) {
    asm volatile(
        "mma.sync.aligned.m16n8k16.row.col.f32.f16.f16.f32 "
        "{%0,%1,%2,%3}, {%4,%5,%6,%7}, {%8,%9}, {%0,%1,%2,%3};"
        : "+f"(c[0]), "+f"(c[1]), "+f"(c[2]), "+f"(c[3])
        : "r"(a[0]), "r"(a[1]), "r"(a[2]), "r"(a[3]), "r"(b0), "r"(b1));
}

__global__ __launch_bounds__(256, 2)
void gemm_mma_kernel(const char* __restrict__ X0,     // fp16 rows, 256B/row
                     const char* __restrict__ X1,     // fp16 rows
                     const char* __restrict__ X2,     // fp16 rows
                     const float* __restrict__ bias,
                     const float* __restrict__ gamma,
                     const float* __restrict__ beta,
                     float* __restrict__ out) {
    extern __shared__ char smem[];
    __shared__ int s_tile;
    int tid = threadIdx.x;
    int wid = tid >> 5, lane = tid & 31;
    int tig = lane & 3, gid = lane >> 2;

    float* sBias  = (float*)(smem + OFF_BIAS);
    float* sGamma = (float*)(smem + OFF_GAMMA);
    float* sBeta  = (float*)(smem + OFF_BETA);
    if (tid < 128) {
        sBias[tid]  = bias[tid];
        sGamma[tid] = gamma[tid];
        sBeta[tid]  = beta[tid];
    }

    // stage pre-converted W: vector memcpy (6528 uint4)
    {
        const uint4* src = (const uint4*)g_wh;
        uint4* dst = (uint4*)smem;
        for (int idx = tid; idx < WH_ELEMS / 8; idx += 256)
            dst[idx] = src[idx];
    }
    __syncthreads();

    for (;;) {
        if (tid == 0) s_tile = atomicAdd(&g_tile_ctr, 1);
        __syncthreads();
        int tile = s_tile;
        if (tile >= NT) break;
        int row0 = tile * 128;

        int r0 = row0 + wid * 16 + gid;
        bool v0 = r0 < NN, v1 = (r0 + 8) < NN;

        float cacc[16][4];
        #pragma unroll
        for (int nt = 0; nt < 16; nt++)
            #pragma unroll
            for (int j = 0; j < 4; j++) cacc[nt][j] = 0.f;

        const char* mw0 = smem;
        const char* mw1 = smem + MAT_BYTES;
        const char* mw2 = smem + 2 * MAT_BYTES;

        #pragma unroll 1
        for (int ks = 0; ks < 8; ks++) {
            int k0 = ks * 16 + tig * 2;
            size_t o0 = (size_t)r0 * 256 + k0 * 2;
            size_t o1 = (size_t)(r0 + 8) * 256 + k0 * 2;
            uint32_t a0[4], a1[4], a2[4];
            a0[0] = v0 ? *(const uint32_t*)(X0 + o0) : 0u;
            a0[1] = v1 ? *(const uint32_t*)(X0 + o1) : 0u;
            a0[2] = v0 ? *(const uint32_t*)(X0 + o0 + 16) : 0u;
            a0[3] = v1 ? *(const uint32_t*)(X0 + o1 + 16) : 0u;
            a1[0] = v0 ? *(const uint32_t*)(X1 + o0) : 0u;
            a1[1] = v1 ? *(const uint32_t*)(X1 + o1) : 0u;
            a1[2] = v0 ? *(const uint32_t*)(X1 + o0 + 16) : 0u;
            a1[3] = v1 ? *(const uint32_t*)(X1 + o1 + 16) : 0u;
            a2[0] = v0 ? *(const uint32_t*)(X2 + o0) : 0u;
            a2[1] = v1 ? *(const uint32_t*)(X2 + o1) : 0u;
            a2[2] = v0 ? *(const uint32_t*)(X2 + o0 + 16) : 0u;
            a2[3] = v1 ? *(const uint32_t*)(X2 + o1 + 16) : 0u;

            #pragma unroll
            for (int nt = 0; nt < 16; nt++) {
                int n = nt * 8 + gid;
                size_t boff = ((size_t)n * KPAD + k0) * 2;
                uint32_t b0 = *(const uint32_t*)(mw0 + boff);
                uint32_t b1 = *(const uint32_t*)(mw0 + boff + 16);
                mma_f16(cacc[nt], a0, b0, b1);
                b0 = *(const uint32_t*)(mw1 + boff);
                b1 = *(const uint32_t*)(mw1 + boff + 16);
                mma_f16(cacc[nt], a1, b0, b1);
                b0 = *(const uint32_t*)(mw2 + boff);
                b1 = *(const uint32_t*)(mw2 + boff + 16);
                mma_f16(cacc[nt], a2, b0, b1);
            }
        }

        #pragma unroll
        for (int h = 0; h < 2; h++) {
            int r = r0 + h * 8;
            float s1 = 0.f, s2 = 0.f;
            #pragma unroll
            for (int nt = 0; nt < 16; nt++) {
                int col = nt * 8 + tig * 2;
                float a = cacc[nt][2 * h + 0] + sBias[col];
                float b = cacc[nt][2 * h + 1] + sBias[col + 1];
                cacc[nt][2 * h + 0] = a;
                cacc[nt][2 * h + 1] = b;
                s1 += a + b;
                s2 += a * a + b * b;
            }
            s1 += __shfl_xor_sync(0xffffffffu, s1, 1);
            s2 += __shfl_xor_sync(0xffffffffu, s2, 1);
            s1 += __shfl_xor_sync(0xffffffffu, s1, 2);
            s2 += __shfl_xor_sync(0xffffffffu, s2, 2);
            float mean = s1 * (1.f / 128.f);
            float var  = s2 * (1.f / 128.f) - mean * mean;
            float inv  = rsqrtf(var + LN_EPS);
            if (r < NN) {
                #pragma unroll
                for (int nt = 0; nt < 16; nt++) {
                    int col = nt * 8 + tig * 2;
                    float2 o;
                    o.x = fmaxf((cacc[nt][2 * h] - mean) * inv * sGamma[col]
                                + sBeta[col], 0.f);
                    o.y = fmaxf((cacc[nt][2 * h + 1] - mean) * inv * sGamma[col + 1]
                                + sBeta[col + 1], 0.f);
                    *(float2*)(out + (size_t)r * 128 + col) = o;
                }
            }
        }
        __syncthreads();
    }
}

// ================= launch =================
extern "C" void kernel_launch(void* const* d_in, const int* in_sizes, int n_in,
                              void* d_out, int out_size) {
    const float* x     = (const float*)d_in[0];
    const float* ew    = (const float*)d_in[1];
    const float* W     = (const float*)d_in[2];
    const float* bias  = (const float*)d_in[3];
    const float* gamma = (const float*)d_in[4];
    const float* beta  = (const float*)d_in[5];
    const int*   ei    = (const int*)d_in[6];
    float* out = (float*)d_out;

    uint2 *Xh, *T1h, *T2h;
    cudaGetSymbolAddress((void**)&Xh, g_xh);
    cudaGetSymbolAddress((void**)&T1h, g_t1h);
    cudaGetSymbolAddress((void**)&T2h, g_t2h);

    cudaFuncSetAttribute(gemm_mma_kernel,
                         cudaFuncAttributeMaxDynamicSharedMemorySize,
                         GEMM_SMEM);

    convert_degree_kernel<<<(NN * 32 + 255) / 256, 256>>>(x, W, ei, ew);
    scan_scatter_kernel<<<SCAN_BLKS, 256>>>(ei, ew);

    spmm_kernel<<<(NN * 32 + 255) / 256, 256>>>(Xh, T1h, nullptr, 1.0f);
    spmm_kernel<<<(NN * 32 + 255) / 256, 256>>>(T1h, T2h, Xh, 2.0f);

    gemm_mma_kernel<<<296, 256, GEMM_SMEM>>>((const char*)Xh, (const char*)T1h,
                                             (const char*)T2h,
                                             bias, gamma, beta, out);
}

// round 16
// speedup vs baseline: 1.1581x; 1.0438x over previous
#include <cuda_runtime.h>
#include <cuda_bf16.h>
#include <cuda_fp16.h>
#include <cstdint>

#define NN 40000
#define EE 640000
#define DD 128
#define LN_EPS 1e-5f
#define SCAN_BLKS 157   // ceil(40000/256)
#define KPAD 136
#define WH_ELEMS (3 * 128 * KPAD)

// ================= device scratch =================
__device__ unsigned long long g_deg[NN];          // packed cnt<<44 | fx24
__device__ __align__(16) float g_dinv[NN];
__device__ int   g_rowptr[NN + 1];
__device__ int   g_cursor[NN];
__device__ int   g_part[SCAN_BLKS];
__device__ int   g_done;
__device__ __align__(16) uint2 g_cv[EE];          // packed {col, val bits}
__device__ __align__(16) uint2 g_xh[(size_t)NN * 32];   // x fp16
__device__ __align__(16) uint2 g_t1h[(size_t)NN * 32];  // T1 fp16
__device__ __align__(16) uint2 g_t2h[(size_t)NN * 32];  // T2 fp16
__device__ __align__(16) __half g_wh[WH_ELEMS];   // W fp16, [p][n][KPAD]
__device__ int   g_tile_ctr;

// ========= K1: fused convert(x->fp16) + W->fp16 transpose + degree =========
__global__ void convert_degree_kernel(const float* __restrict__ x,
                                      const float* __restrict__ W,
                                      const int* __restrict__ ei,
                                      const float* __restrict__ w) {
    int i = blockIdx.x * blockDim.x + threadIdx.x;
    if (i == 0) g_done = 0;
    if (i < NN * 32) {
        float4 v = ((const float4*)x)[i];
        __half2 a = __floats2half2_rn(v.x, v.y);
        __half2 b = __floats2half2_rn(v.z, v.w);
        uint2 u;
        u.x = *reinterpret_cast<uint32_t*>(&a);
        u.y = *reinterpret_cast<uint32_t*>(&b);
        g_xh[i] = u;
    }
    if (i < 3 * 16384) {             // W: [p][k][n] -> g_wh [p][n][KPAD]
        int p = i >> 14;
        int r = i & 16383;
        int k = r >> 7, n = r & 127;
        g_wh[p * 128 * KPAD + n * KPAD + k] = __float2half_rn(W[i]);
    }
    if (i < EE) {
        int r = ei[i];
        if ((unsigned)r < NN) {
            unsigned long long fx =
                (unsigned long long)(w[i] * 16777216.0f);   // w * 2^24
            atomicAdd(&g_deg[r], (1ull << 44) | fx);         // non-returning
        }
    }
}

// ==== K2: fused scan + scatter (two grid-wide spin barriers) ===============
__global__ void scan_scatter_kernel(const int* __restrict__ ei,
                                    const float* __restrict__ w) {
    __shared__ int pex[SCAN_BLKS];
    __shared__ int ws2[8];
    __shared__ int ws[8];
    int tid = threadIdx.x;
    int lane = tid & 31, wid = tid >> 5;
    int b = blockIdx.x;

    // --- local block scan of counts ---
    int i = b * 256 + tid;
    unsigned long long pk = (i < NN) ? g_deg[i] : 0ull;
    int v = (int)(pk >> 44);
    int s = v;
    #pragma unroll
    for (int o = 1; o < 32; o <<= 1) {
        int t = __shfl_up_sync(0xffffffffu, s, o);
        if (lane >= o) s += t;
    }
    if (lane == 31) ws[wid] = s;
    __syncthreads();
    if (wid == 0 && lane < 8) {
        int t = ws[lane];
        #pragma unroll
        for (int o = 1; o < 8; o <<= 1) {
            int u = __shfl_up_sync(0xffu, t, o);
            if (lane >= o) t += u;
        }
        ws[lane] = t;
    }
    __syncthreads();
    int excl_local = s - v + (wid ? ws[wid - 1] : 0);

    // --- barrier 1: publish block totals ---
    if (tid == 0) {
        g_part[b] = ws[7];
        __threadfence();
        atomicAdd(&g_done, 1);
        while (*(volatile int*)&g_done < SCAN_BLKS) { }
        __threadfence();
    }
    __syncthreads();

    // --- parallel exclusive scan of the 157 partials (per block) ---
    int pv = (tid < SCAN_BLKS) ? *(volatile int*)&g_part[tid] : 0;
    int ps = pv;
    #pragma unroll
    for (int o = 1; o < 32; o <<= 1) {
        int t = __shfl_up_sync(0xffffffffu, ps, o);
        if (lane >= o) ps += t;
    }
    if (lane == 31) ws2[wid] = ps;
    __syncthreads();
    if (wid == 0 && lane < 8) {
        int t = ws2[lane];
        #pragma unroll
        for (int o = 1; o < 8; o <<= 1) {
            int u = __shfl_up_sync(0xffu, t, o);
            if (lane >= o) t += u;
        }
        ws2[lane] = t;
    }
    __syncthreads();
    if (tid < SCAN_BLKS)
        pex[tid] = ps - pv + (wid ? ws2[wid - 1] : 0);
    __syncthreads();

    int excl = excl_local + pex[b];
    if (i < NN) {
        g_rowptr[i] = excl;
        g_cursor[i] = excl;
        float dg = (float)(pk & ((1ull << 44) - 1)) * 5.9604644775390625e-8f;
        g_dinv[i] = (dg > 0.f) ? rsqrtf(dg) : 0.f;
        g_deg[i] = 0ull;            // ready for next replay
    }
    if (i == 0) {
        g_tile_ctr = 0;
        g_rowptr[NN] = EE;
    }

    // --- barrier 2: all cursors/dinv visible before scatter ---
    __threadfence();
    __syncthreads();
    if (tid == 0) {
        atomicAdd(&g_done, 1);
        while (*(volatile int*)&g_done < 2 * SCAN_BLKS) { }
        __threadfence();
    }
    __syncthreads();

    // --- scatter phase: stride over edge pairs ---
    const int stride = SCAN_BLKS * 256 * 2;
    for (int e = (b * 256 + tid) * 2; e < EE; e += stride) {
        int2   rr = *(const int2*)(ei + e);
        int2   cc = *(const int2*)(ei + EE + e);
        float2 ww = *(const float2*)(w + e);
        bool ok0 = (unsigned)rr.x < NN && (unsigned)cc.x < NN;
        bool ok1 = (unsigned)rr.y < NN && (unsigned)cc.y < NN;
        float val0 = ok0 ? -g_dinv[rr.x] * ww.x * g_dinv[cc.x] : 0.f;
        float val1 = ok1 ? -g_dinv[rr.y] * ww.y * g_dinv[cc.y] : 0.f;
        int pos0 = ok0 ? atomicAdd(&g_cursor[rr.x], 1) : 0;
        int pos1 = ok1 ? atomicAdd(&g_cursor[rr.y], 1) : 0;
        if (ok0) {
            uint2 cv; cv.x = (uint32_t)cc.x; cv.y = __float_as_uint(val0);
            g_cv[pos0] = cv;
        }
        if (ok1) {
            uint2 cv; cv.x = (uint32_t)cc.y; cv.y = __float_as_uint(val1);
            g_cv[pos1] = cv;
        }
    }
}

// ====== K4/K5: SpMM fp16 in / fp16 out (unroll 2, high occupancy) ==========
__global__ __launch_bounds__(256, 8)
void spmm_kernel(const uint2* __restrict__ Xh,
                 uint2* __restrict__ Yh,
                 const uint2* __restrict__ XsubH,
                 float alpha) {
    int gw = (blockIdx.x * blockDim.x + threadIdx.x) >> 5;
    if (gw >= NN) return;
    int lane = threadIdx.x & 31;
    int s = g_rowptr[gw], e2 = g_rowptr[gw + 1];
    float4 acc = make_float4(0.f, 0.f, 0.f, 0.f);
    int j = s;
    for (; j + 1 < e2; j += 2) {
        uint2 cv0 = g_cv[j], cv1 = g_cv[j + 1];
        uint2 h0 = Xh[(size_t)cv0.x * 32 + lane];
        uint2 h1 = Xh[(size_t)cv1.x * 32 + lane];
        float v0 = __uint_as_float(cv0.y), v1 = __uint_as_float(cv1.y);
        float2 a0 = __half22float2(*reinterpret_cast<__half2*>(&h0.x));
        float2 b0 = __half22float2(*reinterpret_cast<__half2*>(&h0.y));
        float2 a1 = __half22float2(*reinterpret_cast<__half2*>(&h1.x));
        float2 b1 = __half22float2(*reinterpret_cast<__half2*>(&h1.y));
        acc.x += v0 * a0.x; acc.y += v0 * a0.y; acc.z += v0 * b0.x; acc.w += v0 * b0.y;
        acc.x += v1 * a1.x; acc.y += v1 * a1.y; acc.z += v1 * b1.x; acc.w += v1 * b1.y;
    }
    if (j < e2) {
        uint2 cv0 = g_cv[j];
        uint2 h0 = Xh[(size_t)cv0.x * 32 + lane];
        float v0 = __uint_as_float(cv0.y);
        float2 a0 = __half22float2(*reinterpret_cast<__half2*>(&h0.x));
        float2 b0 = __half22float2(*reinterpret_cast<__half2*>(&h0.y));
        acc.x += v0 * a0.x; acc.y += v0 * a0.y; acc.z += v0 * b0.x; acc.w += v0 * b0.y;
    }
    float4 o;
    if (XsubH) {
        uint2 xs = XsubH[(size_t)gw * 32 + lane];
        float2 xa = __half22float2(*reinterpret_cast<__half2*>(&xs.x));
        float2 xb = __half22float2(*reinterpret_cast<__half2*>(&xs.y));
        o.x = alpha * acc.x - xa.x;
        o.y = alpha * acc.y - xa.y;
        o.z = alpha * acc.z - xb.x;
        o.w = alpha * acc.w - xb.y;
    } else {
        o.x = alpha * acc.x; o.y = alpha * acc.y;
        o.z = alpha * acc.z; o.w = alpha * acc.w;
    }
    __half2 ha = __floats2half2_rn(o.x, o.y);
    __half2 hb = __floats2half2_rn(o.z, o.w);
    uint2 u;
    u.x = *reinterpret_cast<uint32_t*>(&ha);
    u.y = *reinterpret_cast<uint32_t*>(&hb);
    Yh[(size_t)gw * 32 + lane] = u;
}

// ====== K6: fp16 mma GEMM (all-fp16 A operands) + bias + LN + ReLU =========
#define NT 313
#define MAT_BYTES (128 * KPAD * 2)
#define OFF_BIAS  (3 * MAT_BYTES)
#define OFF_GAMMA (OFF_BIAS + 512)
#define OFF_BETA  (OFF_GAMMA + 512)
#define GEMM_SMEM (OFF_BETA + 512)      // 105984 (x2 CTAs)

__device__ __forceinline__ void mma_f16(float* c, const uint32_t* a,
                                        uint32_t b0, uint32_t b1) {
    asm volatile(
        "mma.sync.aligned.m16n8k16.row.col.f32.f16.f16.f32 "
        "{%0,%1,%2,%3}, {%4,%5,%6,%7}, {%8,%9}, {%0,%1,%2,%3};"
        : "+f"(c[0]), "+f"(c[1]), "+f"(c[2]), "+f"(c[3])
        : "r"(a[0]), "r"(a[1]), "r"(a[2]), "r"(a[3]), "r"(b0), "r"(b1));
}

__global__ __launch_bounds__(256, 2)
void gemm_mma_kernel(const char* __restrict__ X0,     // fp16 rows, 256B/row
                     const char* __restrict__ X1,     // fp16 rows
                     const char* __restrict__ X2,     // fp16 rows
                     const float* __restrict__ bias,
                     const float* __restrict__ gamma,
                     const float* __restrict__ beta,
                     float* __restrict__ out) {
    extern __shared__ char smem[];
    __shared__ int s_tile;
    int tid = threadIdx.x;
    int wid = tid >> 5, lane = tid & 31;
    int tig = lane & 3, gid = lane >> 2;

    float* sBias  = (float*)(smem + OFF_BIAS);
    float* sGamma = (float*)(smem + OFF_GAMMA);
    float* sBeta  = (float*)(smem + OFF_BETA);
    if (tid < 128) {
        sBias[tid]  = bias[tid];
        sGamma[tid] = gamma[tid];
        sBeta[tid]  = beta[tid];
    }

    // stage pre-converted W: vector memcpy (6528 uint4)
    {
        const uint4* src = (const uint4*)g_wh;
        uint4* dst = (uint4*)smem;
        for (int idx = tid; idx < WH_ELEMS / 8; idx += 256)
            dst[idx] = src[idx];
    }
    __syncthreads();

    for (;;) {
        if (tid == 0) s_tile = atomicAdd(&g_tile_ctr, 1);
        __syncthreads();
        int tile = s_tile;
        if (tile >= NT) break;
        int row0 = tile * 128;

        int r0 = row0 + wid * 16 + gid;
        bool v0 = r0 < NN, v1 = (r0 + 8) < NN;

        float cacc[16][4];
        #pragma unroll
        for (int nt = 0; nt < 16; nt++)
            #pragma unroll
            for (int j = 0; j < 4; j++) cacc[nt][j] = 0.f;

        const char* mw0 = smem;
        const char* mw1 = smem + MAT_BYTES;
        const char* mw2 = smem + 2 * MAT_BYTES;

        #pragma unroll 1
        for (int ks = 0; ks < 8; ks++) {
            int k0 = ks * 16 + tig * 2;
            size_t o0 = (size_t)r0 * 256 + k0 * 2;
            size_t o1 = (size_t)(r0 + 8) * 256 + k0 * 2;
            uint32_t a0[4], a1[4], a2[4];
            a0[0] = v0 ? *(const uint32_t*)(X0 + o0) : 0u;
            a0[1] = v1 ? *(const uint32_t*)(X0 + o1) : 0u;
            a0[2] = v0 ? *(const uint32_t*)(X0 + o0 + 16) : 0u;
            a0[3] = v1 ? *(const uint32_t*)(X0 + o1 + 16) : 0u;
            a1[0] = v0 ? *(const uint32_t*)(X1 + o0) : 0u;
            a1[1] = v1 ? *(const uint32_t*)(X1 + o1) : 0u;
            a1[2] = v0 ? *(const uint32_t*)(X1 + o0 + 16) : 0u;
            a1[3] = v1 ? *(const uint32_t*)(X1 + o1 + 16) : 0u;
            a2[0] = v0 ? *(const uint32_t*)(X2 + o0) : 0u;
            a2[1] = v1 ? *(const uint32_t*)(X2 + o1) : 0u;
            a2[2] = v0 ? *(const uint32_t*)(X2 + o0 + 16) : 0u;
            a2[3] = v1 ? *(const uint32_t*)(X2 + o1 + 16) : 0u;

            #pragma unroll
            for (int nt = 0; nt < 16; nt++) {
                int n = nt * 8 + gid;
                size_t boff = ((size_t)n * KPAD + k0) * 2;
                uint32_t b0 = *(const uint32_t*)(mw0 + boff);
                uint32_t b1 = *(const uint32_t*)(mw0 + boff + 16);
                mma_f16(cacc[nt], a0, b0, b1);
                b0 = *(const uint32_t*)(mw1 + boff);
                b1 = *(const uint32_t*)(mw1 + boff + 16);
                mma_f16(cacc[nt], a1, b0, b1);
                b0 = *(const uint32_t*)(mw2 + boff);
                b1 = *(const uint32_t*)(mw2 + boff + 16);
                mma_f16(cacc[nt], a2, b0, b1);
            }
        }

        #pragma unroll
        for (int h = 0; h < 2; h++) {
            int r = r0 + h * 8;
            float s1 = 0.f, s2 = 0.f;
            #pragma unroll
            for (int nt = 0; nt < 16; nt++) {
                int col = nt * 8 + tig * 2;
                float a = cacc[nt][2 * h + 0] + sBias[col];
                float b = cacc[nt][2 * h + 1] + sBias[col + 1];
                cacc[nt][2 * h + 0] = a;
                cacc[nt][2 * h + 1] = b;
                s1 += a + b;
                s2 += a * a + b * b;
            }
            s1 += __shfl_xor_sync(0xffffffffu, s1, 1);
            s2 += __shfl_xor_sync(0xffffffffu, s2, 1);
            s1 += __shfl_xor_sync(0xffffffffu, s1, 2);
            s2 += __shfl_xor_sync(0xffffffffu, s2, 2);
            float mean = s1 * (1.f / 128.f);
            float var  = s2 * (1.f / 128.f) - mean * mean;
            float inv  = rsqrtf(var + LN_EPS);
            if (r < NN) {
                #pragma unroll
                for (int nt = 0; nt < 16; nt++) {
                    int col = nt * 8 + tig * 2;
                    float2 o;
                    o.x = fmaxf((cacc[nt][2 * h] - mean) * inv * sGamma[col]
                                + sBeta[col], 0.f);
                    o.y = fmaxf((cacc[nt][2 * h + 1] - mean) * inv * sGamma[col + 1]
                                + sBeta[col + 1], 0.f);
                    *(float2*)(out + (size_t)r * 128 + col) = o;
                }
            }
        }
        __syncthreads();
    }
}

// ================= launch =================
extern "C" void kernel_launch(void* const* d_in, const int* in_sizes, int n_in,
                              void* d_out, int out_size) {
    const float* x     = (const float*)d_in[0];
    const float* ew    = (const float*)d_in[1];
    const float* W     = (const float*)d_in[2];
    const float* bias  = (const float*)d_in[3];
    const float* gamma = (const float*)d_in[4];
    const float* beta  = (const float*)d_in[5];
    const int*   ei    = (const int*)d_in[6];
    float* out = (float*)d_out;

    uint2 *Xh, *T1h, *T2h;
    cudaGetSymbolAddress((void**)&Xh, g_xh);
    cudaGetSymbolAddress((void**)&T1h, g_t1h);
    cudaGetSymbolAddress((void**)&T2h, g_t2h);

    cudaFuncSetAttribute(gemm_mma_kernel,
                         cudaFuncAttributeMaxDynamicSharedMemorySize,
                         GEMM_SMEM);

    convert_degree_kernel<<<(NN * 32 + 255) / 256, 256>>>(x, W, ei, ew);
    scan_scatter_kernel<<<SCAN_BLKS, 256>>>(ei, ew);

    spmm_kernel<<<(NN * 32 + 255) / 256, 256>>>(Xh, T1h, nullptr, 1.0f);
    spmm_kernel<<<(NN * 32 + 255) / 256, 256>>>(T1h, T2h, Xh, 2.0f);

    gemm_mma_kernel<<<296, 256, GEMM_SMEM>>>((const char*)Xh, (const char*)T1h,
                                             (const char*)T2h,
                                             bias, gamma, beta, out);
}

// round 17
// speedup vs baseline: 1.1625x; 1.0038x over previous
#include <cuda_runtime.h>
#include <cuda_bf16.h>
#include <cuda_fp16.h>
#include <cstdint>

#define NN 40000
#define EE 640000
#define DD 128
#define LN_EPS 1e-5f
#define SCAN_BLKS 157   // ceil(40000/256)
#define KPAD 136
#define WH_ELEMS (3 * 128 * KPAD)

// ================= device scratch =================
__device__ unsigned long long g_deg[NN];          // packed cnt<<44 | fx24
__device__ __align__(16) float g_dinv[NN];
__device__ int   g_rowptr[NN + 1];
__device__ int   g_cursor[NN];
__device__ int   g_part[SCAN_BLKS];
__device__ int   g_done;
__device__ __align__(16) uint2 g_cv[EE];          // packed {col, val bits}
__device__ __align__(16) uint2 g_xh[(size_t)NN * 32];   // x fp16
__device__ __align__(16) uint2 g_t1h[(size_t)NN * 32];  // T1 fp16
__device__ __align__(16) uint2 g_t2h[(size_t)NN * 32];  // T2 fp16
__device__ __align__(16) __half g_wh[WH_ELEMS];   // W fp16, [p][n][KPAD]
__device__ int   g_tile_ctr;

// ========= K1: fused convert(x->fp16) + W->fp16 transpose + degree =========
__global__ void convert_degree_kernel(const float* __restrict__ x,
                                      const float* __restrict__ W,
                                      const int* __restrict__ ei,
                                      const float* __restrict__ w) {
    int i = blockIdx.x * blockDim.x + threadIdx.x;
    if (i == 0) g_done = 0;
    if (i < NN * 32) {
        float4 v = ((const float4*)x)[i];
        __half2 a = __floats2half2_rn(v.x, v.y);
        __half2 b = __floats2half2_rn(v.z, v.w);
        uint2 u;
        u.x = *reinterpret_cast<uint32_t*>(&a);
        u.y = *reinterpret_cast<uint32_t*>(&b);
        g_xh[i] = u;
    }
    if (i < 3 * 16384) {             // W: [p][k][n] -> g_wh [p][n][KPAD]
        int p = i >> 14;
        int r = i & 16383;
        int k = r >> 7, n = r & 127;
        g_wh[p * 128 * KPAD + n * KPAD + k] = __float2half_rn(W[i]);
    }
    if (i < EE) {
        int r = ei[i];
        if ((unsigned)r < NN) {
            unsigned long long fx =
                (unsigned long long)(w[i] * 16777216.0f);   // w * 2^24
            atomicAdd(&g_deg[r], (1ull << 44) | fx);         // non-returning
        }
    }
}

// ==== K2: fused scan + scatter (two grid-wide spin barriers) ===============
__global__ void scan_scatter_kernel(const int* __restrict__ ei,
                                    const float* __restrict__ w) {
    __shared__ int pex[SCAN_BLKS];
    __shared__ int ws2[8];
    __shared__ int ws[8];
    int tid = threadIdx.x;
    int lane = tid & 31, wid = tid >> 5;
    int b = blockIdx.x;

    // --- local block scan of counts ---
    int i = b * 256 + tid;
    unsigned long long pk = (i < NN) ? g_deg[i] : 0ull;
    int v = (int)(pk >> 44);
    int s = v;
    #pragma unroll
    for (int o = 1; o < 32; o <<= 1) {
        int t = __shfl_up_sync(0xffffffffu, s, o);
        if (lane >= o) s += t;
    }
    if (lane == 31) ws[wid] = s;
    __syncthreads();
    if (wid == 0 && lane < 8) {
        int t = ws[lane];
        #pragma unroll
        for (int o = 1; o < 8; o <<= 1) {
            int u = __shfl_up_sync(0xffu, t, o);
            if (lane >= o) t += u;
        }
        ws[lane] = t;
    }
    __syncthreads();
    int excl_local = s - v + (wid ? ws[wid - 1] : 0);

    // --- barrier 1: publish block totals ---
    if (tid == 0) {
        g_part[b] = ws[7];
        __threadfence();
        atomicAdd(&g_done, 1);
        while (*(volatile int*)&g_done < SCAN_BLKS) { }
        __threadfence();
    }
    __syncthreads();

    // --- parallel exclusive scan of the 157 partials (per block) ---
    int pv = (tid < SCAN_BLKS) ? *(volatile int*)&g_part[tid] : 0;
    int ps = pv;
    #pragma unroll
    for (int o = 1; o < 32; o <<= 1) {
        int t = __shfl_up_sync(0xffffffffu, ps, o);
        if (lane >= o) ps += t;
    }
    if (lane == 31) ws2[wid] = ps;
    __syncthreads();
    if (wid == 0 && lane < 8) {
        int t = ws2[lane];
        #pragma unroll
        for (int o = 1; o < 8; o <<= 1) {
            int u = __shfl_up_sync(0xffu, t, o);
            if (lane >= o) t += u;
        }
        ws2[lane] = t;
    }
    __syncthreads();
    if (tid < SCAN_BLKS)
        pex[tid] = ps - pv + (wid ? ws2[wid - 1] : 0);
    __syncthreads();

    int excl = excl_local + pex[b];
    if (i < NN) {
        g_rowptr[i] = excl;
        g_cursor[i] = excl;
        float dg = (float)(pk & ((1ull << 44) - 1)) * 5.9604644775390625e-8f;
        g_dinv[i] = (dg > 0.f) ? rsqrtf(dg) : 0.f;
        g_deg[i] = 0ull;            // ready for next replay
    }
    if (i == 0) {
        g_tile_ctr = 0;
        g_rowptr[NN] = EE;
    }

    // --- barrier 2: all cursors/dinv visible before scatter ---
    __threadfence();
    __syncthreads();
    if (tid == 0) {
        atomicAdd(&g_done, 1);
        while (*(volatile int*)&g_done < 2 * SCAN_BLKS) { }
        __threadfence();
    }
    __syncthreads();

    // --- scatter phase: stride over edge pairs ---
    const int stride = SCAN_BLKS * 256 * 2;
    for (int e = (b * 256 + tid) * 2; e < EE; e += stride) {
        int2   rr = *(const int2*)(ei + e);
        int2   cc = *(const int2*)(ei + EE + e);
        float2 ww = *(const float2*)(w + e);
        bool ok0 = (unsigned)rr.x < NN && (unsigned)cc.x < NN;
        bool ok1 = (unsigned)rr.y < NN && (unsigned)cc.y < NN;
        float val0 = ok0 ? -g_dinv[rr.x] * ww.x * g_dinv[cc.x] : 0.f;
        float val1 = ok1 ? -g_dinv[rr.y] * ww.y * g_dinv[cc.y] : 0.f;
        int pos0 = ok0 ? atomicAdd(&g_cursor[rr.x], 1) : 0;
        int pos1 = ok1 ? atomicAdd(&g_cursor[rr.y], 1) : 0;
        if (ok0) {
            uint2 cv; cv.x = (uint32_t)cc.x; cv.y = __float_as_uint(val0);
            g_cv[pos0] = cv;
        }
        if (ok1) {
            uint2 cv; cv.x = (uint32_t)cc.y; cv.y = __float_as_uint(val1);
            g_cv[pos1] = cv;
        }
    }
}

// ====== K4/K5: SpMM fp16 gather, HFMA2 + chunked f32 flush ================
__global__ __launch_bounds__(256, 8)
void spmm_kernel(const uint2* __restrict__ Xh,
                 uint2* __restrict__ Yh,
                 const uint2* __restrict__ XsubH,
                 float alpha) {
    int gw = (blockIdx.x * blockDim.x + threadIdx.x) >> 5;
    if (gw >= NN) return;
    int lane = threadIdx.x & 31;
    int s = g_rowptr[gw], e2 = g_rowptr[gw + 1];
    float4 acc = make_float4(0.f, 0.f, 0.f, 0.f);
    int j = s;

    // peel one edge if start is odd (align g_cv to 16B for uint4 loads)
    if ((j & 1) && j < e2) {
        uint2 cv0 = g_cv[j];
        uint2 h0 = Xh[(size_t)cv0.x * 32 + lane];
        float v0 = __uint_as_float(cv0.y);
        float2 a0 = __half22float2(*reinterpret_cast<__half2*>(&h0.x));
        float2 b0 = __half22float2(*reinterpret_cast<__half2*>(&h0.y));
        acc.x += v0 * a0.x; acc.y += v0 * a0.y;
        acc.z += v0 * b0.x; acc.w += v0 * b0.y;
        j++;
    }

    // fast path: 8 edges per chunk, fp16 FMA, f32 flush per chunk
    int nfast = (e2 - j) & ~7;
    int jend = j + nfast;
    const __half2 z16 = __float2half2_rn(0.f);
    for (; j < jend; j += 8) {
        __half2 acc01 = z16, acc23 = z16;
        #pragma unroll
        for (int q = 0; q < 8; q += 2) {
            uint4 cvp = *(const uint4*)&g_cv[j + q];   // 2 edges, broadcast
            uint2 h0 = Xh[(size_t)cvp.x * 32 + lane];
            uint2 h1 = Xh[(size_t)cvp.z * 32 + lane];
            __half2 v0 = __float2half2_rn(__uint_as_float(cvp.y));
            __half2 v1 = __float2half2_rn(__uint_as_float(cvp.w));
            acc01 = __hfma2(*reinterpret_cast<__half2*>(&h0.x), v0, acc01);
            acc23 = __hfma2(*reinterpret_cast<__half2*>(&h0.y), v0, acc23);
            acc01 = __hfma2(*reinterpret_cast<__half2*>(&h1.x), v1, acc01);
            acc23 = __hfma2(*reinterpret_cast<__half2*>(&h1.y), v1, acc23);
        }
        float2 f01 = __half22float2(acc01);
        float2 f23 = __half22float2(acc23);
        acc.x += f01.x; acc.y += f01.y;
        acc.z += f23.x; acc.w += f23.y;
    }

    // remainder: f32 path
    for (; j < e2; j++) {
        uint2 cv0 = g_cv[j];
        uint2 h0 = Xh[(size_t)cv0.x * 32 + lane];
        float v0 = __uint_as_float(cv0.y);
        float2 a0 = __half22float2(*reinterpret_cast<__half2*>(&h0.x));
        float2 b0 = __half22float2(*reinterpret_cast<__half2*>(&h0.y));
        acc.x += v0 * a0.x; acc.y += v0 * a0.y;
        acc.z += v0 * b0.x; acc.w += v0 * b0.y;
    }

    float4 o;
    if (XsubH) {
        uint2 xs = XsubH[(size_t)gw * 32 + lane];
        float2 xa = __half22float2(*reinterpret_cast<__half2*>(&xs.x));
        float2 xb = __half22float2(*reinterpret_cast<__half2*>(&xs.y));
        o.x = alpha * acc.x - xa.x;
        o.y = alpha * acc.y - xa.y;
        o.z = alpha * acc.z - xb.x;
        o.w = alpha * acc.w - xb.y;
    } else {
        o.x = alpha * acc.x; o.y = alpha * acc.y;
        o.z = alpha * acc.z; o.w = alpha * acc.w;
    }
    __half2 ha = __floats2half2_rn(o.x, o.y);
    __half2 hb = __floats2half2_rn(o.z, o.w);
    uint2 u;
    u.x = *reinterpret_cast<uint32_t*>(&ha);
    u.y = *reinterpret_cast<uint32_t*>(&hb);
    Yh[(size_t)gw * 32 + lane] = u;
}

// ====== K6: fp16 mma GEMM (all-fp16 A operands) + bias + LN + ReLU =========
#define NT 313
#define MAT_BYTES (128 * KPAD * 2)
#define OFF_BIAS  (3 * MAT_BYTES)
#define OFF_GAMMA (OFF_BIAS + 512)
#define OFF_BETA  (OFF_GAMMA + 512)
#define GEMM_SMEM (OFF_BETA + 512)      // 105984 (x2 CTAs)

__device__ __forceinline__ void mma_f16(float* c, const uint32_t* a,
                                        uint32_t b0, uint32_t b1) {
    asm volatile(
        "mma.sync.aligned.m16n8k16.row.col.f32.f16.f16.f32 "
        "{%0,%1,%2,%3}, {%4,%5,%6,%7}, {%8,%9}, {%0,%1,%2,%3};"
        : "+f"(c[0]), "+f"(c[1]), "+f"(c[2]), "+f"(c[3])
        : "r"(a[0]), "r"(a[1]), "r"(a[2]), "r"(a[3]), "r"(b0), "r"(b1));
}

__global__ __launch_bounds__(256, 2)
void gemm_mma_kernel(const char* __restrict__ X0,     // fp16 rows, 256B/row
                     const char* __restrict__ X1,     // fp16 rows
                     const char* __restrict__ X2,     // fp16 rows
                     const float* __restrict__ bias,
                     const float* __restrict__ gamma,
                     const float* __restrict__ beta,
                     float* __restrict__ out) {
    extern __shared__ char smem[];
    __shared__ int s_tile;
    int tid = threadIdx.x;
    int wid = tid >> 5, lane = tid & 31;
    int tig = lane & 3, gid = lane >> 2;

    float* sBias  = (float*)(smem + OFF_BIAS);
    float* sGamma = (float*)(smem + OFF_GAMMA);
    float* sBeta  = (float*)(smem + OFF_BETA);
    if (tid < 128) {
        sBias[tid]  = bias[tid];
        sGamma[tid] = gamma[tid];
        sBeta[tid]  = beta[tid];
    }

    // stage pre-converted W: vector memcpy (6528 uint4)
    {
        const uint4* src = (const uint4*)g_wh;
        uint4* dst = (uint4*)smem;
        for (int idx = tid; idx < WH_ELEMS / 8; idx += 256)
            dst[idx] = src[idx];
    }
    __syncthreads();

    for (;;) {
        if (tid == 0) s_tile = atomicAdd(&g_tile_ctr, 1);
        __syncthreads();
        int tile = s_tile;
        if (tile >= NT) break;
        int row0 = tile * 128;

        int r0 = row0 + wid * 16 + gid;
        bool v0 = r0 < NN, v1 = (r0 + 8) < NN;

        float cacc[16][4];
        #pragma unroll
        for (int nt = 0; nt < 16; nt++)
            #pragma unroll
            for (int j = 0; j < 4; j++) cacc[nt][j] = 0.f;

        const char* mw0 = smem;
        const char* mw1 = smem + MAT_BYTES;
        const char* mw2 = smem + 2 * MAT_BYTES;

        #pragma unroll 1
        for (int ks = 0; ks < 8; ks++) {
            int k0 = ks * 16 + tig * 2;
            size_t o0 = (size_t)r0 * 256 + k0 * 2;
            size_t o1 = (size_t)(r0 + 8) * 256 + k0 * 2;
            uint32_t a0[4], a1[4], a2[4];
            a0[0] = v0 ? *(const uint32_t*)(X0 + o0) : 0u;
            a0[1] = v1 ? *(const uint32_t*)(X0 + o1) : 0u;
            a0[2] = v0 ? *(const uint32_t*)(X0 + o0 + 16) : 0u;
            a0[3] = v1 ? *(const uint32_t*)(X0 + o1 + 16) : 0u;
            a1[0] = v0 ? *(const uint32_t*)(X1 + o0) : 0u;
            a1[1] = v1 ? *(const uint32_t*)(X1 + o1) : 0u;
            a1[2] = v0 ? *(const uint32_t*)(X1 + o0 + 16) : 0u;
            a1[3] = v1 ? *(const uint32_t*)(X1 + o1 + 16) : 0u;
            a2[0] = v0 ? *(const uint32_t*)(X2 + o0) : 0u;
            a2[1] = v1 ? *(const uint32_t*)(X2 + o1) : 0u;
            a2[2] = v0 ? *(const uint32_t*)(X2 + o0 + 16) : 0u;
            a2[3] = v1 ? *(const uint32_t*)(X2 + o1 + 16) : 0u;

            #pragma unroll
            for (int nt = 0; nt < 16; nt++) {
                int n = nt * 8 + gid;
                size_t boff = ((size_t)n * KPAD + k0) * 2;
                uint32_t b0 = *(const uint32_t*)(mw0 + boff);
                uint32_t b1 = *(const uint32_t*)(mw0 + boff + 16);
                mma_f16(cacc[nt], a0, b0, b1);
                b0 = *(const uint32_t*)(mw1 + boff);
                b1 = *(const uint32_t*)(mw1 + boff + 16);
                mma_f16(cacc[nt], a1, b0, b1);
                b0 = *(const uint32_t*)(mw2 + boff);
                b1 = *(const uint32_t*)(mw2 + boff + 16);
                mma_f16(cacc[nt], a2, b0, b1);
            }
        }

        #pragma unroll
        for (int h = 0; h < 2; h++) {
            int r = r0 + h * 8;
            float s1 = 0.f, s2 = 0.f;
            #pragma unroll
            for (int nt = 0; nt < 16; nt++) {
                int col = nt * 8 + tig * 2;
                float a = cacc[nt][2 * h + 0] + sBias[col];
                float b = cacc[nt][2 * h + 1] + sBias[col + 1];
                cacc[nt][2 * h + 0] = a;
                cacc[nt][2 * h + 1] = b;
                s1 += a + b;
                s2 += a * a + b * b;
            }
            s1 += __shfl_xor_sync(0xffffffffu, s1, 1);
            s2 += __shfl_xor_sync(0xffffffffu, s2, 1);
            s1 += __shfl_xor_sync(0xffffffffu, s1, 2);
            s2 += __shfl_xor_sync(0xffffffffu, s2, 2);
            float mean = s1 * (1.f / 128.f);
            float var  = s2 * (1.f / 128.f) - mean * mean;
            float inv  = rsqrtf(var + LN_EPS);
            if (r < NN) {
                #pragma unroll
                for (int nt = 0; nt < 16; nt++) {
                    int col = nt * 8 + tig * 2;
                    float2 o;
                    o.x = fmaxf((cacc[nt][2 * h] - mean) * inv * sGamma[col]
                                + sBeta[col], 0.f);
                    o.y = fmaxf((cacc[nt][2 * h + 1] - mean) * inv * sGamma[col + 1]
                                + sBeta[col + 1], 0.f);
                    *(float2*)(out + (size_t)r * 128 + col) = o;
                }
            }
        }
        __syncthreads();
    }
}

// ================= launch =================
extern "C" void kernel_launch(void* const* d_in, const int* in_sizes, int n_in,
                              void* d_out, int out_size) {
    const float* x     = (const float*)d_in[0];
    const float* ew    = (const float*)d_in[1];
    const float* W     = (const float*)d_in[2];
    const float* bias  = (const float*)d_in[3];
    const float* gamma = (const float*)d_in[4];
    const float* beta  = (const float*)d_in[5];
    const int*   ei    = (const int*)d_in[6];
    float* out = (float*)d_out;

    uint2 *Xh, *T1h, *T2h;
    cudaGetSymbolAddress((void**)&Xh, g_xh);
    cudaGetSymbolAddress((void**)&T1h, g_t1h);
    cudaGetSymbolAddress((void**)&T2h, g_t2h);

    cudaFuncSetAttribute(gemm_mma_kernel,
                         cudaFuncAttributeMaxDynamicSharedMemorySize,
                         GEMM_SMEM);

    convert_degree_kernel<<<(NN * 32 + 255) / 256, 256>>>(x, W, ei, ew);
    scan_scatter_kernel<<<SCAN_BLKS, 256>>>(ei, ew);

    spmm_kernel<<<(NN * 32 + 255) / 256, 256>>>(Xh, T1h, nullptr, 1.0f);
    spmm_kernel<<<(NN * 32 + 255) / 256, 256>>>(T1h, T2h, Xh, 2.0f);

    gemm_mma_kernel<<<296, 256, GEMM_SMEM>>>((const char*)Xh, (const char*)T1h,
                                             (const char*)T2h,
                                             bias, gamma, beta, out);
}